// round 4
// baseline (speedup 1.0000x reference)
#include <cuda_runtime.h>

// Problem constants (fixed by the dataset): B=2, N=64, CI=32, CO=32
#define B2 2
#define NP 64
#define CIc 32
#define COc 32
#define CHUNKS 64   // blocks per z; chunk index == c

// Scratch (device globals; no allocs). partials: t=0 ft, t=1..3 GFd(x)
__device__ float g_part[B2][CHUNKS][4][CIc];
__device__ float g_Ua[B2][NP][COc];
__device__ float g_Ub[B2][NP][COc];
__device__ unsigned int g_c1[B2];    // phase-1 arrivals (zero-init)
__device__ unsigned int g_flag[B2];  // Ua/Ub ready
__device__ unsigned int g_c3[B2];    // completion (for reset)

__global__ void __launch_bounds__(256, 1) pc_fused(
    const float* __restrict__ f,
    const float* __restrict__ geom,
    const float* __restrict__ W,
    const void*  __restrict__ nnp,
    float* __restrict__ out)
{
    int z     = blockIdx.x >> 6;
    int chunk = blockIdx.x & 63;     // == c for phase 1, == a for phase 3
    int tid   = threadIdx.x;
    int lane  = tid & 31;
    int w     = tid >> 5;

    __shared__ float gsh[NP][3];
    for (int t = tid; t < NP * 3; t += 256)
        gsh[t / 3][t % 3] = geom[z * NP * 3 + t];
    __syncthreads();

    // ---------------- Phase 1: 64 rows, c = chunk fixed, d varies ----------
    const float* base = f + ((size_t)(z * NP + chunk) * NP) * CIc + lane;
    float a0 = 0.f, a4 = 0.f, a5 = 0.f, a6 = 0.f;
    #pragma unroll
    for (int k = 0; k < 8; k++) {
        int d = w + 8 * k;
        float v = base[d * CIc];     // coalesced
        a0 += v;
        a4 += v * gsh[d][0];
        a5 += v * gsh[d][1];
        a6 += v * gsh[d][2];
    }
    __shared__ float sh[8][4][CIc];
    sh[w][0][lane] = a0; sh[w][1][lane] = a4;
    sh[w][2][lane] = a5; sh[w][3][lane] = a6;
    __syncthreads();
    if (tid < 128) {
        int t = tid >> 5;
        float s = 0.f;
        #pragma unroll
        for (int k = 0; k < 8; k++) s += sh[k][t][lane];
        g_part[z][chunk][t][lane] = s;
    }
    __threadfence();
    __syncthreads();
    if (tid == 0) atomicAdd(&g_c1[z], 1u);

    // ---------------- Phase 2: one block per z computes Ua/Ub --------------
    if (chunk == 0) {
        if (tid == 0) {
            volatile unsigned int* p = &g_c1[z];
            while (*p < (unsigned)CHUNKS) { __nanosleep(32); }
            __threadfence();
        }
        __syncthreads();

        // red: 0=ft, 1..3=GFd[x], 4..6=GFs[x] (GFs from c-weighted part0)
        __shared__ float red[7][CIc];
        if (tid < 224) {
            int t = tid >> 5;
            float acc = 0.f;
            if (t == 0) {
                #pragma unroll 8
                for (int p = 0; p < CHUNKS; p++) acc += g_part[z][p][0][lane];
            } else if (t < 4) {
                #pragma unroll 8
                for (int p = 0; p < CHUNKS; p++) acc += g_part[z][p][t][lane];
            } else {
                int x = t - 4;
                #pragma unroll 8
                for (int p = 0; p < CHUNKS; p++)
                    acc += gsh[p][x] * g_part[z][p][0][lane];
            }
            red[t][lane] = acc;
        }
        __syncthreads();

        __shared__ float Aa[3][COc], Ab[3][COc], Cst[3][COc];
        for (int p8 = w; p8 < 96; p8 += 8) {
            int x = p8 >> 5, i = p8 & 31;
            const float* Wb = W + (size_t)x * (6 * COc * CIc) + i * CIc + lane;
            float w1 = Wb[0 * COc * CIc];
            float w2 = Wb[1 * COc * CIc];
            float w3 = Wb[2 * COc * CIc];
            float w4 = Wb[3 * COc * CIc];
            float w5 = Wb[4 * COc * CIc];
            float w6 = Wb[5 * COc * CIc];
            float ftl = red[0][lane];
            float gd  = red[1 + x][lane];   // GFd
            float gs  = red[4 + x][lane];   // GFs
            float aa = (w1 + w2 + w3) * ftl;
            float ab = (w1 - w4 - w5) * ftl;
            float cc = (w2 + w4) * gs + (w3 + w5) * gd + w6 * (gd - gs);
            #pragma unroll
            for (int o = 16; o; o >>= 1) {
                aa += __shfl_xor_sync(0xFFFFFFFFu, aa, o);
                ab += __shfl_xor_sync(0xFFFFFFFFu, ab, o);
                cc += __shfl_xor_sync(0xFFFFFFFFu, cc, o);
            }
            if (lane == 0) { Aa[x][i] = aa; Ab[x][i] = ab; Cst[x][i] = cc; }
        }
        __syncthreads();

        // n_norm: tolerate int32 or float32 encoding
        int   iv = *(const int*)nnp;
        float nn = (iv >= 1 && iv <= (1 << 20)) ? (float)iv : *(const float*)nnp;
        float s  = rsqrtf(6.0f * nn * nn);

        __shared__ float cv[COc];
        if (tid < COc)
            cv[tid] = s * (Cst[0][tid] + Cst[1][tid] + Cst[2][tid]);
        __syncthreads();

        #pragma unroll
        for (int t = tid; t < NP * COc; t += 256) {
            int a = t >> 5, i = t & 31;
            float g0 = gsh[a][0], g1 = gsh[a][1], g2 = gsh[a][2];
            g_Ua[z][a][i] = cv[i] - s * (g0 * Aa[0][i] + g1 * Aa[1][i] + g2 * Aa[2][i]);
            g_Ub[z][a][i] =         s * (g0 * Ab[0][i] + g1 * Ab[1][i] + g2 * Ab[2][i]);
        }
        __threadfence();
        __syncthreads();
        if (tid == 0) atomicExch(&g_flag[z], 1u);
    } else {
        if (tid == 0) {
            volatile unsigned int* p = &g_flag[z];
            while (*p == 0u) { __nanosleep(32); }
            __threadfence();
        }
        __syncthreads();
    }

    // ---------------- Phase 3: out[z,a=chunk,b,i] = Ua[a,i] + Ub[b,i] ------
    {
        float ua = g_Ua[z][chunk][lane];
        float* o = out + ((size_t)(z * NP + chunk) * NP) * COc + lane;
        #pragma unroll
        for (int b = w; b < NP; b += 8)
            o[b * COc] = ua + g_Ub[z][b][lane];
    }

    // ---------------- Reset barrier state for next graph replay ------------
    __syncthreads();
    if (tid == 0) {
        unsigned int v = atomicAdd(&g_c3[z], 1u);
        if (v == (unsigned)(CHUNKS - 1)) {
            atomicExch(&g_c1[z], 0u);
            atomicExch(&g_flag[z], 0u);
            atomicExch(&g_c3[z], 0u);
        }
    }
}

// ---------------------------------------------------------------------------
extern "C" void kernel_launch(void* const* d_in, const int* in_sizes, int n_in,
                              void* d_out, int out_size) {
    const float* features = (const float*)d_in[0]; // [2,64,64,32]
    const float* geometry = (const float*)d_in[1]; // [2,64,3]
    const float* W        = (const float*)d_in[2]; // [3,6144]
    const void*  n_norm   = d_in[3];               // scalar
    float* out = (float*)d_out;                    // [2,64,64,32]

    pc_fused<<<B2 * CHUNKS, 256>>>(features, geometry, W, n_norm, out);
}

// round 5
// speedup vs baseline: 1.4961x; 1.4961x over previous
#include <cuda_runtime.h>

// Problem constants (fixed by the dataset): B=2, N=64, CI=32, CO=32
#define B2 2
#define NP 64
#define CIc 32
#define COc 32
#define K1_BLKS_PER_Z 32
#define ROWS_PER_BLK (NP * NP / K1_BLKS_PER_Z)   // 128

// Scratch: per-block partial sums of the 7 weighted feature reductions
// [z][block][t][j], t: 0=ft, 1..3=GFs(x) (c-weighted), 4..6=GFd(x) (d-weighted)
__device__ float g_part[B2][K1_BLKS_PER_Z][7][CIc];

// ---------------------------------------------------------------------------
// K1: streaming weighted reduction over features.
// Row r = c*64 + d. Weights per row: {1, g[c].xyz, g[d].xyz}.
// grid = 64 (2 z * 32), block = 256 (8 warps * 32 lanes; lane = channel j)
// ---------------------------------------------------------------------------
__global__ void pc_k1(const float* __restrict__ f,
                      const float* __restrict__ geom) {
    int z   = blockIdx.x >> 5;
    int blk = blockIdx.x & 31;
    int j   = threadIdx.x & 31;
    int w   = threadIdx.x >> 5;

    __shared__ float gsh[NP][3];
    for (int t = threadIdx.x; t < NP * 3; t += 256)
        gsh[t / 3][t % 3] = geom[z * NP * 3 + t];
    __syncthreads();

    int r0 = blk * ROWS_PER_BLK;
    const float* base = f + ((size_t)z * NP * NP + r0) * CIc + j;

    float a0 = 0.f, a1 = 0.f, a2 = 0.f, a3 = 0.f, a4 = 0.f, a5 = 0.f, a6 = 0.f;
    #pragma unroll
    for (int k = 0; k < ROWS_PER_BLK / 8; k++) {
        int rr = w + 8 * k;            // 0..127
        float v = base[rr * CIc];      // coalesced: lanes j consecutive
        int r = r0 + rr;
        int c = r >> 6, d = r & 63;
        a0 += v;
        a1 += v * gsh[c][0];
        a2 += v * gsh[c][1];
        a3 += v * gsh[c][2];
        a4 += v * gsh[d][0];
        a5 += v * gsh[d][1];
        a6 += v * gsh[d][2];
    }

    __shared__ float sh[8][7][CIc];
    sh[w][0][j] = a0; sh[w][1][j] = a1; sh[w][2][j] = a2; sh[w][3][j] = a3;
    sh[w][4][j] = a4; sh[w][5][j] = a5; sh[w][6][j] = a6;
    __syncthreads();

    if (threadIdx.x < 224) {
        int t  = threadIdx.x >> 5;     // 0..6
        int jj = threadIdx.x & 31;
        float s = 0.f;
        #pragma unroll
        for (int k = 0; k < 8; k++) s += sh[k][t][jj];
        g_part[z][blk][t][jj] = s;
    }
}

// ---------------------------------------------------------------------------
// K2: one block per (z, a). Re-reduce partials (L2), per-THREAD (x,i) dot
// products over j (no shuffles), then write out[z,a,b,i] = Ua[a,i] + Ub[b,i].
// grid = 128, block = 256
// ---------------------------------------------------------------------------
__global__ void pc_k2(const float* __restrict__ geom,
                      const float* __restrict__ W,
                      const void*  __restrict__ nnp,
                      float* __restrict__ out) {
    int z    = blockIdx.x >> 6;
    int a    = blockIdx.x & 63;
    int tid  = threadIdx.x;
    int lane = tid & 31;
    int w    = tid >> 5;

    __shared__ float gsh[NP][3];
    __shared__ __align__(16) float red[7][CIc];  // ft, GFs[3], GFd[3]
    __shared__ float Aa[3][COc], Ab[3][COc], Cst[3][COc];
    __shared__ float UaS[COc];

    for (int t = tid; t < NP * 3; t += 256)
        gsh[t / 3][t % 3] = geom[z * NP * 3 + t];

    if (tid < 224) {
        int t  = tid >> 5;                 // 0..6
        int jj = tid & 31;
        float acc = 0.f;
        #pragma unroll
        for (int p = 0; p < K1_BLKS_PER_Z; p++)
            acc += g_part[z][p][t][jj];    // coalesced lanes, independent loads
        red[t][jj] = acc;
    }
    __syncthreads();

    // Per-thread (x,i): 32-length dot products, float4 everywhere, no shuffles
    if (tid < 96) {
        int x = tid >> 5, i = tid & 31;
        const float4* Wb = reinterpret_cast<const float4*>(
            W + (size_t)x * (6 * COc * CIc) + i * CIc);          // 8 float4 per matrix row
        const float4* ftv = reinterpret_cast<const float4*>(&red[0][0]);
        const float4* gsv = reinterpret_cast<const float4*>(&red[1 + x][0]);
        const float4* gdv = reinterpret_cast<const float4*>(&red[4 + x][0]);
        float aa = 0.f, ab = 0.f, cc = 0.f;
        #pragma unroll
        for (int q = 0; q < 8; q++) {
            float4 w1 = Wb[0 * 256 + q];
            float4 w2 = Wb[1 * 256 + q];
            float4 w3 = Wb[2 * 256 + q];
            float4 w4 = Wb[3 * 256 + q];
            float4 w5 = Wb[4 * 256 + q];
            float4 w6 = Wb[5 * 256 + q];
            float4 ft4 = ftv[q], gs4 = gsv[q], gd4 = gdv[q];
            aa += (w1.x + w2.x + w3.x) * ft4.x + (w1.y + w2.y + w3.y) * ft4.y
                + (w1.z + w2.z + w3.z) * ft4.z + (w1.w + w2.w + w3.w) * ft4.w;
            ab += (w1.x - w4.x - w5.x) * ft4.x + (w1.y - w4.y - w5.y) * ft4.y
                + (w1.z - w4.z - w5.z) * ft4.z + (w1.w - w4.w - w5.w) * ft4.w;
            cc += (w2.x + w4.x) * gs4.x + (w3.x + w5.x) * gd4.x + w6.x * (gd4.x - gs4.x)
                + (w2.y + w4.y) * gs4.y + (w3.y + w5.y) * gd4.y + w6.y * (gd4.y - gs4.y)
                + (w2.z + w4.z) * gs4.z + (w3.z + w5.z) * gd4.z + w6.z * (gd4.z - gs4.z)
                + (w2.w + w4.w) * gs4.w + (w3.w + w5.w) * gd4.w + w6.w * (gd4.w - gs4.w);
        }
        Aa[x][i] = aa; Ab[x][i] = ab; Cst[x][i] = cc;
    }
    __syncthreads();

    // n_norm: tolerate int32 or float32 encoding
    int   iv = *(const int*)nnp;
    float nn = (iv >= 1 && iv <= (1 << 20)) ? (float)iv : *(const float*)nnp;
    float s  = rsqrtf(6.0f * nn * nn);

    if (tid < COc) {
        float cv = s * (Cst[0][tid] + Cst[1][tid] + Cst[2][tid]);
        float g0 = gsh[a][0], g1 = gsh[a][1], g2 = gsh[a][2];
        UaS[tid] = cv - s * (g0 * Aa[0][tid] + g1 * Aa[1][tid] + g2 * Aa[2][tid]);
        Ab[0][tid] *= s; Ab[1][tid] *= s; Ab[2][tid] *= s;   // pre-scale
    }
    __syncthreads();

    float ua  = UaS[lane];
    float ab0 = Ab[0][lane], ab1 = Ab[1][lane], ab2 = Ab[2][lane];
    float* o = out + ((size_t)(z * NP + a) * NP) * COc + lane;
    #pragma unroll
    for (int b = w; b < NP; b += 8)
        o[b * COc] = ua + gsh[b][0] * ab0 + gsh[b][1] * ab1 + gsh[b][2] * ab2;
}

// ---------------------------------------------------------------------------
extern "C" void kernel_launch(void* const* d_in, const int* in_sizes, int n_in,
                              void* d_out, int out_size) {
    const float* features = (const float*)d_in[0]; // [2,64,64,32]
    const float* geometry = (const float*)d_in[1]; // [2,64,3]
    const float* W        = (const float*)d_in[2]; // [3,6144]
    const void*  n_norm   = d_in[3];               // scalar
    float* out = (float*)d_out;                    // [2,64,64,32]

    pc_k1<<<B2 * K1_BLKS_PER_Z, 256>>>(features, geometry);
    pc_k2<<<B2 * NP, 256>>>(geometry, W, n_norm, out);
}